// round 4
// baseline (speedup 1.0000x reference)
#include <cuda_runtime.h>
#include <cuda_bf16.h>

// SoftPerspectiveShader: fused sample_textures + softmax_rgb_blend
// R2/R3: speculative prefetch of first-valid fragment's bary + face colors.
// With zbuf sorted ascending, z_inv is descending, so the first valid k is the
// argmax of masked z_inv => it is (almost always) the only fragment whose
// softmax weight survives exp underflow at GAMMA=1e-4. Prefetching its gather
// data right after pix_to_face arrives removes the serial
// (expf-chain -> gather) dependency that left DRAM at 66% busy in R1.

#define SIGMA_F 1e-4f
#define GAMMA_F 1e-4f
#define ZNEAR_F 1.0f
#define ZFAR_F  100.0f
#define EPS_F   1e-10f

__global__ __launch_bounds__(256) void soft_shader_kernel(
    const int4*   __restrict__ p2f,    // [P][2] int4  (K=8)
    const float*  __restrict__ bary,   // [P][8][3]
    const float4* __restrict__ zbuf,   // [P][2] float4
    const float4* __restrict__ dists,  // [P][2] float4
    const float*  __restrict__ fcol,   // [F][3][3]
    float4*       __restrict__ out,    // [P]
    int P)
{
    int p = blockIdx.x * blockDim.x + threadIdx.x;
    if (p >= P) return;

    // ---- load faces first; everything speculative hangs off this ----
    const int4 fa = p2f[2 * p], fb = p2f[2 * p + 1];
    int faces[8] = {fa.x, fa.y, fa.z, fa.w, fb.x, fb.y, fb.z, fb.w};

    // first-valid selection (SEL chain, no dynamic reg indexing)
    int  k0    = 7;
    int  fsel  = faces[7];
    bool hasv  = faces[7] >= 0;
#pragma unroll
    for (int k = 6; k >= 0; k--) {
        bool v = faces[k] >= 0;
        k0   = v ? k        : k0;
        fsel = v ? faces[k] : fsel;
        hasv = hasv || v;
    }
    int fclamped = fsel >= 0 ? fsel : 0;

    // ---- speculative prefetch: bary + face colors for k0 (issues NOW) ----
    const float* bc0 = bary + (size_t)p * 24 + (size_t)k0 * 3;
    float pb0 = __ldg(bc0 + 0), pb1 = __ldg(bc0 + 1), pb2 = __ldg(bc0 + 2);
    const float* fc0 = fcol + (size_t)fclamped * 9;
    float pf0 = __ldg(fc0 + 0), pf1 = __ldg(fc0 + 1), pf2 = __ldg(fc0 + 2);
    float pf3 = __ldg(fc0 + 3), pf4 = __ldg(fc0 + 4), pf5 = __ldg(fc0 + 5);
    float pf6 = __ldg(fc0 + 6), pf7 = __ldg(fc0 + 7), pf8 = __ldg(fc0 + 8);

    // ---- bulk loads (overlap with the prefetch above) ----
    const float4 za = zbuf[2 * p],  zb = zbuf[2 * p + 1];
    const float4 da = dists[2 * p], db = dists[2 * p + 1];
    float zv[8] = {za.x, za.y, za.z, za.w, zb.x, zb.y, zb.z, zb.w};
    float dv[8] = {da.x, da.y, da.z, da.w, db.x, db.y, db.z, db.w};

    // z_inv_max: first valid fragment holds the max of masked z_inv
    // (z sorted ascending => z_inv descending). Same arithmetic as reference.
    float zsel = 0.0f;
#pragma unroll
    for (int k = 7; k >= 0; k--) zsel = (faces[k] >= 0) ? zv[k] : zsel;
    float zinv_k0 = (ZFAR_F - zsel) / (ZFAR_F - ZNEAR_F);
    float zmax = hasv ? fmaxf(zinv_k0, EPS_F) : EPS_F;

    float delta = fmaxf(expf((EPS_F - zmax) / GAMMA_F), EPS_F);
    float denom = delta;
    float keep  = 1.0f;
    float r = 0.0f, g = 0.0f, b = 0.0f;

#pragma unroll
    for (int k = 0; k < 8; k++) {
        bool  m  = faces[k] >= 0;
        // sigmoid(-d/sigma) = 1/(1+exp(d/sigma))
        float pr = m ? (1.0f / (1.0f + expf(dv[k] / SIGMA_F))) : 0.0f;
        keep *= (1.0f - pr);
        float zi = m ? ((ZFAR_F - zv[k]) / (ZFAR_F - ZNEAR_F)) : 0.0f;
        float w  = pr * expf((zi - zmax) / GAMMA_F);
        denom += w;

        if (k == k0) {
            // fast path: prefetched gather (w may be 0; adds 0 then)
            float t0 = pb0 * pf0 + pb1 * pf3 + pb2 * pf6;
            float t1 = pb0 * pf1 + pb1 * pf4 + pb2 * pf7;
            float t2 = pb0 * pf2 + pb1 * pf5 + pb2 * pf8;
            r += w * t0; g += w * t1; b += w * t2;
        } else if (w > 0.0f) {
            // rare: another fragment within ~87*GAMMA of zmax
            const float* bc = bary + (size_t)p * 24 + (size_t)k * 3;
            float b0 = bc[0], b1 = bc[1], b2 = bc[2];
            const float* fc = fcol + (size_t)faces[k] * 9;
            float t0 = b0 * fc[0] + b1 * fc[3] + b2 * fc[6];
            float t1 = b0 * fc[1] + b1 * fc[4] + b2 * fc[7];
            float t2 = b0 * fc[2] + b1 * fc[5] + b2 * fc[8];
            r += w * t0; g += w * t1; b += w * t2;
        }
    }

    float inv = 1.0f / denom;
    float4 o;
    o.x = (r + delta) * inv;   // background = (1,1,1)
    o.y = (g + delta) * inv;
    o.z = (b + delta) * inv;
    o.w = keep;                // 1 - alpha
    out[p] = o;
}

extern "C" void kernel_launch(void* const* d_in, const int* in_sizes, int n_in,
                              void* d_out, int out_size) {
    const int*   p2f   = (const int*)d_in[0];
    const float* bary  = (const float*)d_in[1];
    const float* zbufp = (const float*)d_in[2];
    const float* dist  = (const float*)d_in[3];
    const float* fcol  = (const float*)d_in[4];
    int P = in_sizes[0] / 8;   // N*H*W pixels

    int threads = 256;
    int blocks  = (P + threads - 1) / threads;
    soft_shader_kernel<<<blocks, threads>>>(
        (const int4*)p2f, bary, (const float4*)zbufp, (const float4*)dist,
        fcol, (float4*)d_out, P);
}